// round 1
// baseline (speedup 1.0000x reference)
#include <cuda_runtime.h>
#include <cstdint>

// Problem constants (fixed-shape problem)
#define IN_F   64
#define OUT_F  64
#define MODES  32
#define NB     65          // 1 + 2*MODES
#define KTOT   4096        // IN_F * 64 (sin/cos only; "ones" folded into bias)
#define M_TILE 128
#define PI_F   3.14159265358979323846f

// SMEM layout strides (floats), padded for bank-conflict-free fragment access
#define AS_STRIDE 136              // A stored [j][row]: (tig*136+gid)%32 -> tig*8+gid unique
#define AS_BUF    (64 * AS_STRIDE) // one stage: 64 k-values x 128 rows (+pad)
#define BS_STRIDE 72               // B stored [k][o]: (tig*72+gid)%32 -> tig*8+gid unique
#define BS_BUF    (64 * BS_STRIDE)
#define XS_STRIDE 68               // x tile [row][i]

// Scratch (device globals — no allocation allowed)
__device__ __align__(16) float g_packB[KTOT * OUT_F];  // 1 MB repacked tf32 coeffs [k][o]
__device__ float g_bias_eff[OUT_F];

__device__ __forceinline__ uint32_t to_tf32_u(float x) {
    uint32_t r;
    asm("cvt.rna.tf32.f32 %0, %1;" : "=r"(r) : "f"(x));
    return r;
}

__device__ __forceinline__ void mma_tf32(float* d,
                                         uint32_t a0, uint32_t a1, uint32_t a2, uint32_t a3,
                                         uint32_t b0, uint32_t b1) {
    asm volatile(
        "mma.sync.aligned.m16n8k8.row.col.f32.tf32.tf32.f32 "
        "{%0,%1,%2,%3}, {%4,%5,%6,%7}, {%8,%9}, {%0,%1,%2,%3};"
        : "+f"(d[0]), "+f"(d[1]), "+f"(d[2]), "+f"(d[3])
        : "r"(a0), "r"(a1), "r"(a2), "r"(a3), "r"(b0), "r"(b1));
}

// ---------------------------------------------------------------------------
// Prep kernel 1: repack coeffs[o][i][b] (b=1..64 = sin_1..sin_32, cos_1..cos_32)
// into g_packB[k][o] with k = i*64 + j (j<32: sin_{j+1}; j>=32: cos_{j-31}).
// Source b index = 1 + j for both halves. Values pre-rounded to tf32 (RNA).
// ---------------------------------------------------------------------------
__global__ void repack_kernel(const float* __restrict__ coeffs) {
    int idx = blockIdx.x * blockDim.x + threadIdx.x;   // over [KTOT][OUT_F]
    if (idx >= KTOT * OUT_F) return;
    int k = idx >> 6;
    int o = idx & 63;
    int i = k >> 6;
    int j = k & 63;
    float v = coeffs[(size_t)o * (IN_F * NB) + i * NB + 1 + j];
    g_packB[idx] = __uint_as_float(to_tf32_u(v));
}

// Prep kernel 2: effective bias = bias[o] + sum_i coeffs[o][i][0] (the "ones" slice)
__global__ void bias_kernel(const float* __restrict__ coeffs, const float* __restrict__ bias) {
    int o = threadIdx.x;
    if (o >= OUT_F) return;
    float s = bias[o];
    for (int i = 0; i < IN_F; ++i) s += coeffs[(size_t)o * (IN_F * NB) + i * NB];
    g_bias_eff[o] = s;
}

// ---------------------------------------------------------------------------
// Stage producer: threads 0..127 generate the basis tile for input-feature i
// (sincos + rotation recurrence, tf32-rounded) into AsN[j][row];
// threads 128..255 stream the coeff tile for feature i into BsN[j][o].
// ---------------------------------------------------------------------------
__device__ __forceinline__ void stage_produce(int tid, int i, float* AsN, float* BsN,
                                              const float* xs) {
    if (tid < 128) {
        int r = tid;
        float f = PI_F * xs[r * XS_STRIDE + i];
        float s, c;
        sincosf(f, &s, &c);
        float sm_ = s, cm_ = c;
#pragma unroll
        for (int m = 0; m < 32; ++m) {
            AsN[m * AS_STRIDE + r]        = __uint_as_float(to_tf32_u(sm_));  // sin_{m+1}
            AsN[(32 + m) * AS_STRIDE + r] = __uint_as_float(to_tf32_u(cm_));  // cos_{m+1}
            float ns = sm_ * c + cm_ * s;
            float nc = cm_ * c - sm_ * s;
            sm_ = ns; cm_ = nc;
        }
    } else {
        int t2 = tid - 128;
        const float4* src = reinterpret_cast<const float4*>(g_packB + (size_t)i * (64 * OUT_F));
#pragma unroll
        for (int w = 0; w < 8; ++w) {
            int idx = t2 + w * 128;        // 0..1023 float4s = 64 k-rows x 16
            int j = idx >> 4, o4 = idx & 15;
            float4 v = src[idx];
            *reinterpret_cast<float4*>(BsN + j * BS_STRIDE + o4 * 4) = v;
        }
    }
}

// ---------------------------------------------------------------------------
// Main fused kernel: per CTA 128 tokens x all 64 outputs, K streamed over the
// 64 input features (K_chunk = 64 per stage), double-buffered SMEM.
// 8 warps, each owns a 16-row slab; full N=64 in accumulators (32 f32/thread).
// ---------------------------------------------------------------------------
__global__ void __launch_bounds__(256, 1)
fkan_main(const float* __restrict__ x, float* __restrict__ out) {
    extern __shared__ float smf[];
    float* As = smf;                       // 2 * AS_BUF
    float* Bs = As + 2 * AS_BUF;           // 2 * BS_BUF
    float* xs = Bs + 2 * BS_BUF;           // 128 * XS_STRIDE

    int tid  = threadIdx.x;
    int m0   = blockIdx.x * M_TILE;
    int lane = tid & 31;
    int warp = tid >> 5;
    int gid  = lane >> 2;
    int tig  = lane & 3;

    // Load x tile [128][64] -> xs (coalesced float4)
    const float4* xsrc = reinterpret_cast<const float4*>(x + (size_t)m0 * IN_F);
#pragma unroll
    for (int w = 0; w < 8; ++w) {
        int idx = tid + w * 256;           // 0..2047 float4s
        int r = idx >> 4, c4 = idx & 15;
        float4 v = xsrc[idx];
        *reinterpret_cast<float4*>(xs + r * XS_STRIDE + c4 * 4) = v;
    }
    __syncthreads();

    float acc[8][4];
#pragma unroll
    for (int a = 0; a < 8; ++a)
#pragma unroll
        for (int b = 0; b < 4; ++b) acc[a][b] = 0.f;

    // Prologue: fill buffer 0
    stage_produce(tid, 0, As, Bs, xs);
    __syncthreads();

    int r_lo = warp * 16 + gid;
    int r_hi = r_lo + 8;

    for (int i = 0; i < IN_F; ++i) {
        int buf = i & 1;
        const float* AsC = As + buf * AS_BUF;
        const float* BsC = Bs + buf * BS_BUF;

        // Produce next stage into the other buffer (overlaps with MMA below)
        if (i + 1 < IN_F)
            stage_produce(tid, i + 1, As + (buf ^ 1) * AS_BUF, Bs + (buf ^ 1) * BS_BUF, xs);

        // 64 k-values this stage = 8 k-steps of the m16n8k8 MMA
#pragma unroll
        for (int kt = 0; kt < 8; ++kt) {
            int k0 = kt * 8;
            uint32_t a0 = __float_as_uint(AsC[(k0 + tig)     * AS_STRIDE + r_lo]);
            uint32_t a1 = __float_as_uint(AsC[(k0 + tig)     * AS_STRIDE + r_hi]);
            uint32_t a2 = __float_as_uint(AsC[(k0 + tig + 4) * AS_STRIDE + r_lo]);
            uint32_t a3 = __float_as_uint(AsC[(k0 + tig + 4) * AS_STRIDE + r_hi]);
#pragma unroll
            for (int nt = 0; nt < 8; ++nt) {
                int n0 = nt * 8;
                uint32_t b0 = __float_as_uint(BsC[(k0 + tig)     * BS_STRIDE + n0 + gid]);
                uint32_t b1 = __float_as_uint(BsC[(k0 + tig + 4) * BS_STRIDE + n0 + gid]);
                mma_tf32(acc[nt], a0, a1, a2, a3, b0, b1);
            }
        }
        __syncthreads();
    }

    // Epilogue: add effective bias, store fp32 (float2 per row-half per n-tile)
    int gr_lo = m0 + r_lo;
    int gr_hi = m0 + r_hi;
#pragma unroll
    for (int nt = 0; nt < 8; ++nt) {
        int c0 = nt * 8 + tig * 2;
        float b0v = g_bias_eff[c0];
        float b1v = g_bias_eff[c0 + 1];
        float2 lo = make_float2(acc[nt][0] + b0v, acc[nt][1] + b1v);
        float2 hi = make_float2(acc[nt][2] + b0v, acc[nt][3] + b1v);
        *reinterpret_cast<float2*>(out + (size_t)gr_lo * OUT_F + c0) = lo;
        *reinterpret_cast<float2*>(out + (size_t)gr_hi * OUT_F + c0) = hi;
    }
}

// ---------------------------------------------------------------------------
extern "C" void kernel_launch(void* const* d_in, const int* in_sizes, int n_in,
                              void* d_out, int out_size) {
    const float* x      = (const float*)d_in[0];   // [N, 64] f32
    const float* coeffs = (const float*)d_in[1];   // [64, 64, 65] f32
    const float* bias   = (const float*)d_in[2];   // [64] f32
    float* out = (float*)d_out;                    // [N, 64] f32

    int ntok = in_sizes[0] / IN_F;

    // Prep: repack coeffs (tf32) + fold "ones" slice into bias
    repack_kernel<<<(KTOT * OUT_F + 255) / 256, 256>>>(coeffs);
    bias_kernel<<<1, 64>>>(coeffs, bias);

    int smem_bytes = (2 * AS_BUF + 2 * BS_BUF + 128 * XS_STRIDE) * (int)sizeof(float);
    cudaFuncSetAttribute(fkan_main, cudaFuncAttributeMaxDynamicSharedMemorySize, smem_bytes);
    fkan_main<<<ntok / M_TILE, 256, smem_bytes>>>(x, out);
}

// round 3
// speedup vs baseline: 1.5377x; 1.5377x over previous
#include <cuda_runtime.h>
#include <cstdint>

// Fixed-shape problem: N=65536 tokens, IN=OUT=64, 32 modes.
#define IN_F 64
#define OUT_F 64
#define NB 65
#define PI_F 3.14159265358979323846f

#define M_TILE 256
#define NSTAGE 64
#define BK_STRIDE 72                        // floats per k-row of B tile (bank pad)
#define B_TILE_FLOATS (64 * BK_STRIDE)      // 4608 floats = 18432 B
#define B_TILE_BYTES (B_TILE_FLOATS * 4)
#define XS_STRIDE 261                       // 256 rows + pad (conflict-free scatter)

// Device-global scratch (no allocation allowed)
__device__ __align__(128) float g_packB[NSTAGE * B_TILE_FLOATS];  // ~4.7 MB? no: 64*4608*4 = 1.18 MB
__device__ float g_bias_eff[OUT_F];

// ---------------------------------------------------------------------------
static __device__ __forceinline__ uint32_t to_tf32_u(float x) {
    uint32_t r; asm("cvt.rna.tf32.f32 %0, %1;" : "=r"(r) : "f"(x)); return r;
}
static __device__ __forceinline__ uint32_t smem_u32(const void* p) {
    return (uint32_t)__cvta_generic_to_shared(p);
}
static __device__ __forceinline__ void mbar_init(uint32_t a, uint32_t cnt) {
    asm volatile("mbarrier.init.shared.b64 [%0], %1;" :: "r"(a), "r"(cnt) : "memory");
}
static __device__ __forceinline__ void mbar_expect_tx(uint32_t a, uint32_t bytes) {
    asm volatile("mbarrier.arrive.expect_tx.shared.b64 _, [%0], %1;" :: "r"(a), "r"(bytes) : "memory");
}
static __device__ __forceinline__ void mbar_wait(uint32_t a, uint32_t parity) {
    asm volatile(
        "{\n\t.reg .pred P;\n"
        "LW%=:\n\t"
        "mbarrier.try_wait.parity.shared.b64 P, [%0], %1;\n\t"
        "@!P bra LW%=;\n\t}"
        :: "r"(a), "r"(parity) : "memory");
}
static __device__ __forceinline__ void bulk_g2s(uint32_t dst, const void* src,
                                                uint32_t bytes, uint32_t mbar) {
    asm volatile(
        "cp.async.bulk.shared::cluster.global.mbarrier::complete_tx::bytes [%0], [%1], %2, [%3];"
        :: "r"(dst), "l"(src), "r"(bytes), "r"(mbar) : "memory");
}
static __device__ __forceinline__ void mma_tf32(float* d,
                                                uint32_t a0, uint32_t a1, uint32_t a2, uint32_t a3,
                                                uint32_t b0, uint32_t b1) {
    asm volatile(
        "mma.sync.aligned.m16n8k8.row.col.f32.tf32.tf32.f32 "
        "{%0,%1,%2,%3}, {%4,%5,%6,%7}, {%8,%9}, {%0,%1,%2,%3};"
        : "+f"(d[0]), "+f"(d[1]), "+f"(d[2]), "+f"(d[3])
        : "r"(a0), "r"(a1), "r"(a2), "r"(a3), "r"(b0), "r"(b1));
}

// ---------------------------------------------------------------------------
// Prep 1: per-stage B images [i][k][72pad], tf32(RNA)-rounded.
// k<32 -> sin_{k+1} (coeff b=1+k); k>=32 -> cos_{k-31} (coeff b=1+k).
__global__ void repack_kernel(const float* __restrict__ coeffs) {
    int idx = blockIdx.x * blockDim.x + threadIdx.x;   // over 64 i x 64 k x 64 o
    if (idx >= NSTAGE * 64 * 64) return;
    int i = idx >> 12;
    int k = (idx >> 6) & 63;
    int o = idx & 63;
    float v = coeffs[(size_t)o * (IN_F * NB) + i * NB + 1 + k];
    g_packB[(size_t)i * B_TILE_FLOATS + k * BK_STRIDE + o] = __uint_as_float(to_tf32_u(v));
}

// Prep 2: fold the "ones" basis slice into the bias.
__global__ void bias_kernel(const float* __restrict__ coeffs, const float* __restrict__ bias) {
    int o = threadIdx.x;
    if (o >= OUT_F) return;
    float s = bias[o];
    for (int i = 0; i < IN_F; ++i) s += coeffs[(size_t)o * (IN_F * NB) + i * NB];
    g_bias_eff[o] = s;
}

// ---------------------------------------------------------------------------
// Main kernel: 256 threads (8 warps), 256 tokens per CTA, warp owns 32 rows x
// all 64 outputs. A fragments computed in registers (sincos + rotation chain),
// B streamed via double-buffered cp.async.bulk, mma.sync tf32 m16n8k8.
__global__ void __launch_bounds__(256, 1)
fkan_main(const float* __restrict__ x, float* __restrict__ out) {
    extern __shared__ float smf[];
    float* xs = smf;                                   // [64][XS_STRIDE]
    float* Bs = smf + NSTAGE * XS_STRIDE;              // 2 x B_TILE_FLOATS
    uint32_t mb0 = smem_u32(Bs + 2 * B_TILE_FLOATS);
    uint32_t mb1 = mb0 + 8;
    uint32_t BsU = smem_u32(Bs);

    int tid  = threadIdx.x;
    int warp = tid >> 5;
    int lane = tid & 31;
    int gid  = lane >> 2;     // 0..7
    int tig  = lane & 3;      // 0..3
    int m0   = blockIdx.x * M_TILE;

    if (tid == 0) { mbar_init(mb0, 1); mbar_init(mb1, 1); }

    // Load x tile: coalesced float4 from gmem, scatter-transpose into xs[i][row]
    const float4* xsrc = reinterpret_cast<const float4*>(x + (size_t)m0 * IN_F);
#pragma unroll
    for (int w = 0; w < 16; ++w) {
        int idx4 = tid + w * 256;          // 4096 float4s = 256 rows x 16
        int row = idx4 >> 4;
        int i0 = (idx4 & 15) * 4;
        float4 v = xsrc[idx4];
        xs[(i0 + 0) * XS_STRIDE + row] = v.x;
        xs[(i0 + 1) * XS_STRIDE + row] = v.y;
        xs[(i0 + 2) * XS_STRIDE + row] = v.z;
        xs[(i0 + 3) * XS_STRIDE + row] = v.w;
    }
    __syncthreads();

    // Prologue: kick off B loads for stages 0 and 1
    if (tid == 0) {
        mbar_expect_tx(mb0, B_TILE_BYTES);
        bulk_g2s(BsU, g_packB, B_TILE_BYTES, mb0);
        mbar_expect_tx(mb1, B_TILE_BYTES);
        bulk_g2s(BsU + B_TILE_BYTES, g_packB + B_TILE_FLOATS, B_TILE_BYTES, mb1);
    }

    float acc0[8][4], acc1[8][4];          // mt0 (rows gid,gid+8), mt1 (rows +16,+24)
#pragma unroll
    for (int nt = 0; nt < 8; ++nt)
#pragma unroll
        for (int q = 0; q < 4; ++q) { acc0[nt][q] = 0.f; acc1[nt][q] = 0.f; }

    int rbase = warp * 32 + gid;
    float tigf = (float)(tig + 1);
    int bo = tig * BK_STRIDE + gid;        // base float offset for B fragments

#pragma unroll 1
    for (int i = 0; i < NSTAGE; ++i) {
        // ---- A chains (independent of B arrival; overlaps bulk latency) ----
        float s[4], c[4], s4[4], c4[4];
#pragma unroll
        for (int r = 0; r < 4; ++r) {
            float a = PI_F * xs[i * XS_STRIDE + rbase + 8 * r];
            __sincosf(tigf * a, &s[r], &c[r]);     // mode tig+1
            __sincosf(4.0f * a, &s4[r], &c4[r]);   // rotation step (+4 modes)
        }

        mbar_wait(i & 1 ? mb1 : mb0, (i >> 1) & 1);
        const float* Bb = Bs + (i & 1) * B_TILE_FLOATS;

#pragma unroll
        for (int j = 0; j < 4; ++j) {
            // chain captures: t=2j (k=8j+tig), t=2j+1 (k=8j+tig+4); sin & cos halves
            uint32_t sa[4], ca[4], sb[4], cb[4];
#pragma unroll
            for (int r = 0; r < 4; ++r) {
                sa[r] = to_tf32_u(s[r]); ca[r] = to_tf32_u(c[r]);
                float ns = fmaf(s[r], c4[r], c[r] * s4[r]);
                c[r] = fmaf(c[r], c4[r], -s[r] * s4[r]);
                s[r] = ns;
                sb[r] = to_tf32_u(s[r]); cb[r] = to_tf32_u(c[r]);
                ns = fmaf(s[r], c4[r], c[r] * s4[r]);
                c[r] = fmaf(c[r], c4[r], -s[r] * s4[r]);
                s[r] = ns;
            }
            const float* B0 = Bb + (8 * j) * BK_STRIDE + bo;        // sin rows (kt=j)
            const float* B1 = Bb + (32 + 8 * j) * BK_STRIDE + bo;   // cos rows (kt=j+4)
#pragma unroll
            for (int nt = 0; nt < 8; ++nt) {
                uint32_t b0 = __float_as_uint(B0[nt * 8]);
                uint32_t b1 = __float_as_uint(B0[4 * BK_STRIDE + nt * 8]);
                mma_tf32(acc0[nt], sa[0], sa[1], sb[0], sb[1], b0, b1);
                mma_tf32(acc1[nt], sa[2], sa[3], sb[2], sb[3], b0, b1);
                uint32_t e0 = __float_as_uint(B1[nt * 8]);
                uint32_t e1 = __float_as_uint(B1[4 * BK_STRIDE + nt * 8]);
                mma_tf32(acc0[nt], ca[0], ca[1], cb[0], cb[1], e0, e1);
                mma_tf32(acc1[nt], ca[2], ca[3], cb[2], cb[3], e0, e1);
            }
        }
        __syncthreads();   // all warps done with buffer (i&1) before overwrite
        if (i + 2 < NSTAGE && tid == 0) {
            uint32_t mb = (i & 1) ? mb1 : mb0;
            mbar_expect_tx(mb, B_TILE_BYTES);
            bulk_g2s(BsU + (i & 1) * B_TILE_BYTES,
                     g_packB + (size_t)(i + 2) * B_TILE_FLOATS, B_TILE_BYTES, mb);
        }
    }

    // ---- Epilogue: bias + fp32 stores (rows rbase+{0,8,16,24}) ----
    int c0 = tig * 2;
#pragma unroll
    for (int nt = 0; nt < 8; ++nt) {
        float bv0 = g_bias_eff[nt * 8 + c0];
        float bv1 = g_bias_eff[nt * 8 + c0 + 1];
        float* p0 = out + (size_t)(m0 + rbase) * OUT_F + nt * 8 + c0;
        float* p1 = out + (size_t)(m0 + rbase + 8) * OUT_F + nt * 8 + c0;
        float* p2 = out + (size_t)(m0 + rbase + 16) * OUT_F + nt * 8 + c0;
        float* p3 = out + (size_t)(m0 + rbase + 24) * OUT_F + nt * 8 + c0;
        *reinterpret_cast<float2*>(p0) = make_float2(acc0[nt][0] + bv0, acc0[nt][1] + bv1);
        *reinterpret_cast<float2*>(p1) = make_float2(acc0[nt][2] + bv0, acc0[nt][3] + bv1);
        *reinterpret_cast<float2*>(p2) = make_float2(acc1[nt][0] + bv0, acc1[nt][1] + bv1);
        *reinterpret_cast<float2*>(p3) = make_float2(acc1[nt][2] + bv0, acc1[nt][3] + bv1);
    }
}

// ---------------------------------------------------------------------------
extern "C" void kernel_launch(void* const* d_in, const int* in_sizes, int n_in,
                              void* d_out, int out_size) {
    const float* x      = (const float*)d_in[0];   // [N, 64] f32
    const float* coeffs = (const float*)d_in[1];   // [64, 64, 65] f32
    const float* bias   = (const float*)d_in[2];   // [64] f32
    float* out = (float*)d_out;

    int ntok = in_sizes[0] / IN_F;

    repack_kernel<<<(NSTAGE * 64 * 64 + 255) / 256, 256>>>(coeffs);
    bias_kernel<<<1, 64>>>(coeffs, bias);

    int smem_bytes = (NSTAGE * XS_STRIDE + 2 * B_TILE_FLOATS) * 4 + 16;
    cudaFuncSetAttribute(fkan_main, cudaFuncAttributeMaxDynamicSharedMemorySize, smem_bytes);
    fkan_main<<<ntok / M_TILE, 256, smem_bytes>>>(x, out);
}

// round 4
// speedup vs baseline: 2.4395x; 1.5864x over previous
#include <cuda_runtime.h>
#include <cuda_fp16.h>
#include <cstdint>

// Fixed-shape problem: N=65536 tokens, IN=OUT=64, 32 modes.
#define IN_F 64
#define OUT_F 64
#define NB 65
#define PI_F 3.14159265358979323846f

#define M_TILE 256
#define NSTAGE 64
#define BP_STRIDE 72                    // u32 per k-pair row (bank pad)
#define B_TILE_U32 (32 * BP_STRIDE)     // 32 k-pairs x 72 = 2304 u32 = 9216 B
#define B_TILE_BYTES (B_TILE_U32 * 4)
#define XS_STRIDE 261                   // 256 rows + pad

// Device-global scratch (no allocation allowed)
__device__ __align__(128) uint32_t g_packB[NSTAGE * B_TILE_U32];  // fp16x2 coeff images
__device__ float g_bias_eff[OUT_F];

// ---------------------------------------------------------------------------
static __device__ __forceinline__ uint32_t smem_u32(const void* p) {
    return (uint32_t)__cvta_generic_to_shared(p);
}
static __device__ __forceinline__ void mbar_init(uint32_t a, uint32_t cnt) {
    asm volatile("mbarrier.init.shared.b64 [%0], %1;" :: "r"(a), "r"(cnt) : "memory");
}
static __device__ __forceinline__ void mbar_expect_tx(uint32_t a, uint32_t bytes) {
    asm volatile("mbarrier.arrive.expect_tx.shared.b64 _, [%0], %1;" :: "r"(a), "r"(bytes) : "memory");
}
static __device__ __forceinline__ void mbar_wait(uint32_t a, uint32_t parity) {
    asm volatile(
        "{\n\t.reg .pred P;\n"
        "LW%=:\n\t"
        "mbarrier.try_wait.parity.shared.b64 P, [%0], %1;\n\t"
        "@!P bra LW%=;\n\t}"
        :: "r"(a), "r"(parity) : "memory");
}
static __device__ __forceinline__ void bulk_g2s(uint32_t dst, const void* src,
                                                uint32_t bytes, uint32_t mbar) {
    asm volatile(
        "cp.async.bulk.shared::cluster.global.mbarrier::complete_tx::bytes [%0], [%1], %2, [%3];"
        :: "r"(dst), "l"(src), "r"(bytes), "r"(mbar) : "memory");
}
static __device__ __forceinline__ void mma_f16(float* d,
        uint32_t a0, uint32_t a1, uint32_t a2, uint32_t a3,
        uint32_t b0, uint32_t b1) {
    asm volatile(
        "mma.sync.aligned.m16n8k16.row.col.f32.f16.f16.f32 "
        "{%0,%1,%2,%3}, {%4,%5,%6,%7}, {%8,%9}, {%0,%1,%2,%3};"
        : "+f"(d[0]), "+f"(d[1]), "+f"(d[2]), "+f"(d[3])
        : "r"(a0), "r"(a1), "r"(a2), "r"(a3), "r"(b0), "r"(b1));
}
static __device__ __forceinline__ uint32_t pack_h2(float lo, float hi) {
    __half2 h = __floats2half2_rn(lo, hi);       // .x (low bits) = lo
    return *reinterpret_cast<uint32_t*>(&h);
}

// ---------------------------------------------------------------------------
// Prep 1: per-stage B images [i][kpair][72pad], fp16x2 packed along k (RN).
// k<32 -> sin_{k+1}; k>=32 -> cos_{k-31}; both map to coeff b-index 1+k.
__global__ void repack_kernel(const float* __restrict__ coeffs) {
    int idx = blockIdx.x * blockDim.x + threadIdx.x;  // 64 i x 32 p x 64 o
    if (idx >= NSTAGE * 32 * 64) return;
    int i = idx >> 11;
    int p = (idx >> 6) & 31;
    int o = idx & 63;
    const float* base = coeffs + (size_t)o * (IN_F * NB) + i * NB + 1 + 2 * p;
    g_packB[(size_t)i * B_TILE_U32 + p * BP_STRIDE + o] = pack_h2(base[0], base[1]);
}

// Prep 2: fold the "ones" basis slice into the bias.
__global__ void bias_kernel(const float* __restrict__ coeffs, const float* __restrict__ bias) {
    int o = threadIdx.x;
    if (o >= OUT_F) return;
    float s = bias[o];
    for (int i = 0; i < IN_F; ++i) s += coeffs[(size_t)o * (IN_F * NB) + i * NB];
    g_bias_eff[o] = s;
}

// ---------------------------------------------------------------------------
// Main: 256 threads (8 warps), 256 tokens/CTA; warp owns 32 rows x all 64 out.
// A fragments (fp16x2 mode-pairs) computed in registers; B double-buffered via
// cp.async.bulk; mma.sync fp16 m16n8k16 with fp32 accumulation.
__global__ void __launch_bounds__(256, 1)
fkan_main(const float* __restrict__ x, float* __restrict__ out) {
    extern __shared__ float smf[];
    float* xs = smf;                                    // [64][XS_STRIDE]
    uint32_t* Bs = (uint32_t*)(smf + NSTAGE * XS_STRIDE); // 2 x B_TILE_U32
    uint32_t mb0 = smem_u32(Bs + 2 * B_TILE_U32);
    uint32_t mb1 = mb0 + 8;
    uint32_t BsU = smem_u32(Bs);

    int tid  = threadIdx.x;
    int warp = tid >> 5;
    int lane = tid & 31;
    int gid  = lane >> 2;     // 0..7
    int tig  = lane & 3;      // 0..3
    int m0   = blockIdx.x * M_TILE;

    if (tid == 0) { mbar_init(mb0, 1); mbar_init(mb1, 1); }

    // Load x tile: coalesced float4, scatter-transpose into xs[i][row]
    const float4* xsrc = reinterpret_cast<const float4*>(x + (size_t)m0 * IN_F);
#pragma unroll
    for (int w = 0; w < 16; ++w) {
        int idx4 = tid + w * 256;
        int row = idx4 >> 4;
        int i0 = (idx4 & 15) * 4;
        float4 v = xsrc[idx4];
        xs[(i0 + 0) * XS_STRIDE + row] = v.x;
        xs[(i0 + 1) * XS_STRIDE + row] = v.y;
        xs[(i0 + 2) * XS_STRIDE + row] = v.z;
        xs[(i0 + 3) * XS_STRIDE + row] = v.w;
    }
    __syncthreads();

    // Prologue: B loads for stages 0 and 1
    if (tid == 0) {
        mbar_expect_tx(mb0, B_TILE_BYTES);
        bulk_g2s(BsU, g_packB, B_TILE_BYTES, mb0);
        mbar_expect_tx(mb1, B_TILE_BYTES);
        bulk_g2s(BsU + B_TILE_BYTES, g_packB + B_TILE_U32, B_TILE_BYTES, mb1);
    }

    float acc0[8][4], acc1[8][4];
#pragma unroll
    for (int nt = 0; nt < 8; ++nt)
#pragma unroll
        for (int q = 0; q < 4; ++q) { acc0[nt][q] = 0.f; acc1[nt][q] = 0.f; }

    int rbase = warp * 32 + gid;
    float m0f = (float)(2 * tig + 1);     // base mode for this thread's k-pairs
    int bo = tig * BP_STRIDE + gid;       // base u32 offset for B fragments

#pragma unroll 1
    for (int i = 0; i < NSTAGE; ++i) {
        // ---- A chains: per row, half2 mode-pairs (m0+8t, m0+8t+1), t=0..3 ----
        uint32_t pS[4][4], pC[4][4];
#pragma unroll
        for (int r = 0; r < 4; ++r) {
            float a = PI_F * xs[i * XS_STRIDE + rbase + 8 * r];
            float s1, c1; __sincosf(a, &s1, &c1);
            float sA, cA; __sincosf(m0f * a, &sA, &cA);     // mode m0 = 2tig+1
            float sB = fmaf(sA, c1,  cA * s1);              // mode m0+1
            float cB = fmaf(cA, c1, -sA * s1);
            float s2 = 2.f * s1 * c1, c2 = fmaf(-2.f * s1, s1, 1.f);
            float s4 = 2.f * s2 * c2, c4 = fmaf(-2.f * s2, s2, 1.f);
            float s8 = 2.f * s4 * c4, c8 = fmaf(-2.f * s4, s4, 1.f);
#pragma unroll
            for (int t = 0; t < 4; ++t) {
                pS[r][t] = pack_h2(sA, sB);
                pC[r][t] = pack_h2(cA, cB);
                float ns = fmaf(sA, c8,  cA * s8);
                cA = fmaf(cA, c8, -sA * s8); sA = ns;
                ns = fmaf(sB, c8,  cB * s8);
                cB = fmaf(cB, c8, -sB * s8); sB = ns;
            }
        }

        mbar_wait(i & 1 ? mb1 : mb0, (i >> 1) & 1);
        const uint32_t* Bb = Bs + (i & 1) * B_TILE_U32;

        // 4 k16-steps: j=0,1 use sin pairs (t=2jj,2jj+1); j=2,3 use cos pairs
#pragma unroll
        for (int h = 0; h < 2; ++h) {
#pragma unroll
            for (int jj = 0; jj < 2; ++jj) {
                int j = h * 2 + jj;
                uint32_t a0, a1, a2, a3, a4, a5, a6, a7;
                if (h == 0) {
                    a0 = pS[0][2*jj]; a1 = pS[1][2*jj]; a2 = pS[0][2*jj+1]; a3 = pS[1][2*jj+1];
                    a4 = pS[2][2*jj]; a5 = pS[3][2*jj]; a6 = pS[2][2*jj+1]; a7 = pS[3][2*jj+1];
                } else {
                    a0 = pC[0][2*jj]; a1 = pC[1][2*jj]; a2 = pC[0][2*jj+1]; a3 = pC[1][2*jj+1];
                    a4 = pC[2][2*jj]; a5 = pC[3][2*jj]; a6 = pC[2][2*jj+1]; a7 = pC[3][2*jj+1];
                }
                const uint32_t* Bp = Bb + (8 * j) * BP_STRIDE + bo;
#pragma unroll
                for (int nt = 0; nt < 8; ++nt) {
                    uint32_t b0 = Bp[nt * 8];
                    uint32_t b1 = Bp[4 * BP_STRIDE + nt * 8];
                    mma_f16(acc0[nt], a0, a1, a2, a3, b0, b1);
                    mma_f16(acc1[nt], a4, a5, a6, a7, b0, b1);
                }
            }
        }
        __syncthreads();   // all warps done with buffer (i&1) before refill
        if (i + 2 < NSTAGE && tid == 0) {
            uint32_t mb = (i & 1) ? mb1 : mb0;
            mbar_expect_tx(mb, B_TILE_BYTES);
            bulk_g2s(BsU + (i & 1) * B_TILE_BYTES,
                     g_packB + (size_t)(i + 2) * B_TILE_U32, B_TILE_BYTES, mb);
        }
    }

    // ---- Epilogue: bias + fp32 stores (rows rbase+{0,8,16,24}) ----
    int c0 = tig * 2;
#pragma unroll
    for (int nt = 0; nt < 8; ++nt) {
        float bv0 = g_bias_eff[nt * 8 + c0];
        float bv1 = g_bias_eff[nt * 8 + c0 + 1];
        float* p0 = out + (size_t)(m0 + rbase) * OUT_F + nt * 8 + c0;
        float* p1 = out + (size_t)(m0 + rbase + 8) * OUT_F + nt * 8 + c0;
        float* p2 = out + (size_t)(m0 + rbase + 16) * OUT_F + nt * 8 + c0;
        float* p3 = out + (size_t)(m0 + rbase + 24) * OUT_F + nt * 8 + c0;
        *reinterpret_cast<float2*>(p0) = make_float2(acc0[nt][0] + bv0, acc0[nt][1] + bv1);
        *reinterpret_cast<float2*>(p1) = make_float2(acc0[nt][2] + bv0, acc0[nt][3] + bv1);
        *reinterpret_cast<float2*>(p2) = make_float2(acc1[nt][0] + bv0, acc1[nt][1] + bv1);
        *reinterpret_cast<float2*>(p3) = make_float2(acc1[nt][2] + bv0, acc1[nt][3] + bv1);
    }
}

// ---------------------------------------------------------------------------
extern "C" void kernel_launch(void* const* d_in, const int* in_sizes, int n_in,
                              void* d_out, int out_size) {
    const float* x      = (const float*)d_in[0];   // [N, 64] f32
    const float* coeffs = (const float*)d_in[1];   // [64, 64, 65] f32
    const float* bias   = (const float*)d_in[2];   // [64] f32
    float* out = (float*)d_out;

    int ntok = in_sizes[0] / IN_F;

    repack_kernel<<<(NSTAGE * 32 * 64 + 255) / 256, 256>>>(coeffs);
    bias_kernel<<<1, 64>>>(coeffs, bias);

    int smem_bytes = (NSTAGE * XS_STRIDE) * 4 + 2 * B_TILE_BYTES + 16;
    cudaFuncSetAttribute(fkan_main, cudaFuncAttributeMaxDynamicSharedMemorySize, smem_bytes);
    fkan_main<<<ntok / M_TILE, 256, smem_bytes>>>(x, out);
}

// round 5
// speedup vs baseline: 2.5645x; 1.0512x over previous
#include <cuda_runtime.h>
#include <cuda_fp16.h>
#include <cstdint>

// Fixed-shape problem: N=65536 tokens, IN=OUT=64, 32 modes.
#define IN_F 64
#define OUT_F 64
#define NB 65
#define PI_F 3.14159265358979323846f

#define M_TILE 256
#define NSTAGE 64
#define B_TILE_U32 2048                 // 32 lanes x 64 u32 (fragment-ordered)
#define B_TILE_BYTES (B_TILE_U32 * 4)   // 8192 B per stage
#define XS_STRIDE 261                   // 256 rows + pad

// Device-global scratch (no allocation allowed)
__device__ __align__(128) uint32_t g_packB[NSTAGE * B_TILE_U32];  // fragment-ordered fp16x2
__device__ float g_bias_eff[OUT_F];

// ---------------------------------------------------------------------------
static __device__ __forceinline__ uint32_t smem_u32(const void* p) {
    return (uint32_t)__cvta_generic_to_shared(p);
}
static __device__ __forceinline__ void mbar_init(uint32_t a, uint32_t cnt) {
    asm volatile("mbarrier.init.shared.b64 [%0], %1;" :: "r"(a), "r"(cnt) : "memory");
}
static __device__ __forceinline__ void mbar_expect_tx(uint32_t a, uint32_t bytes) {
    asm volatile("mbarrier.arrive.expect_tx.shared.b64 _, [%0], %1;" :: "r"(a), "r"(bytes) : "memory");
}
static __device__ __forceinline__ void mbar_wait(uint32_t a, uint32_t parity) {
    asm volatile(
        "{\n\t.reg .pred P;\n"
        "LW%=:\n\t"
        "mbarrier.try_wait.parity.shared.b64 P, [%0], %1;\n\t"
        "@!P bra LW%=;\n\t}"
        :: "r"(a), "r"(parity) : "memory");
}
static __device__ __forceinline__ void bulk_g2s(uint32_t dst, const void* src,
                                                uint32_t bytes, uint32_t mbar) {
    asm volatile(
        "cp.async.bulk.shared::cluster.global.mbarrier::complete_tx::bytes [%0], [%1], %2, [%3];"
        :: "r"(dst), "l"(src), "r"(bytes), "r"(mbar) : "memory");
}
static __device__ __forceinline__ void mma_f16(float* d,
        uint32_t a0, uint32_t a1, uint32_t a2, uint32_t a3,
        uint32_t b0, uint32_t b1) {
    asm volatile(
        "mma.sync.aligned.m16n8k16.row.col.f32.f16.f16.f32 "
        "{%0,%1,%2,%3}, {%4,%5,%6,%7}, {%8,%9}, {%0,%1,%2,%3};"
        : "+f"(d[0]), "+f"(d[1]), "+f"(d[2]), "+f"(d[3])
        : "r"(a0), "r"(a1), "r"(a2), "r"(a3), "r"(b0), "r"(b1));
}
static __device__ __forceinline__ uint32_t pack_h2(float lo, float hi) {
    __half2 h = __floats2half2_rn(lo, hi);       // .x (low bits) = lo
    return *reinterpret_cast<uint32_t*>(&h);
}

// ---------------------------------------------------------------------------
// Prep 1: fragment-ordered per-stage B images.
// Per stage i, per lane, 16 chunks of 16B (4 u32). Chunk q = j*4 + np holds,
// for nt0=2np, nt1=2np+1:
//   u0 = b0(nt0) [k-pair row 8j+tig],  u1 = b1(nt0) [row 8j+tig+4],
//   u2 = b0(nt1),                      u3 = b1(nt1)
// where b(row p, o) packs coeff b-indices (1+2p, 2+2p) for output o = 8nt+gid.
// Chunk placed at q ^ (lane & 15) for conflict-free LDS.128.
__global__ void repack_kernel(const float* __restrict__ coeffs) {
    int idx = blockIdx.x * blockDim.x + threadIdx.x;  // 64 i x 32 lane x 16 q x 4 u
    if (idx >= NSTAGE * 32 * 16 * 4) return;
    int u    = idx & 3;
    int q    = (idx >> 2) & 15;
    int lane = (idx >> 6) & 31;
    int i    = idx >> 11;
    int gid = lane >> 2, tig = lane & 3;
    int j = q >> 2, np = q & 3;
    int nt = 2 * np + (u >> 1);
    int p  = 8 * j + tig + ((u & 1) ? 4 : 0);   // k-pair row
    int o  = 8 * nt + gid;
    const float* base = coeffs + (size_t)o * (IN_F * NB) + i * NB + 1 + 2 * p;
    g_packB[(size_t)i * B_TILE_U32 + lane * 64 + ((q ^ (lane & 15)) * 4) + u]
        = pack_h2(base[0], base[1]);
}

// Prep 2: fold the "ones" basis slice into the bias.
__global__ void bias_kernel(const float* __restrict__ coeffs, const float* __restrict__ bias) {
    int o = threadIdx.x;
    if (o >= OUT_F) return;
    float s = bias[o];
    for (int i = 0; i < IN_F; ++i) s += coeffs[(size_t)o * (IN_F * NB) + i * NB];
    g_bias_eff[o] = s;
}

// ---------------------------------------------------------------------------
// Main: 256 threads (8 warps), 256 tokens/CTA; warp owns 32 rows x all 64 out.
// A fragments computed in registers; B (fragment-ordered) double-buffered via
// cp.async.bulk, consumed with 16 LDS.128/thread/stage; mma.sync fp16 k16.
__global__ void __launch_bounds__(256, 1)
fkan_main(const float* __restrict__ x, float* __restrict__ out) {
    extern __shared__ float smf[];
    float* xs = smf;                                      // [64][XS_STRIDE]
    uint32_t* Bs = (uint32_t*)(smf + NSTAGE * XS_STRIDE); // 2 x B_TILE_U32
    uint32_t mb0 = smem_u32(Bs + 2 * B_TILE_U32);
    uint32_t mb1 = mb0 + 8;
    uint32_t BsU = smem_u32(Bs);

    int tid  = threadIdx.x;
    int warp = tid >> 5;
    int lane = tid & 31;
    int gid  = lane >> 2;     // 0..7
    int tig  = lane & 3;      // 0..3
    int m0   = blockIdx.x * M_TILE;

    if (tid == 0) { mbar_init(mb0, 1); mbar_init(mb1, 1); }

    // Load x tile: coalesced float4, scatter-transpose into xs[i][row]
    const float4* xsrc = reinterpret_cast<const float4*>(x + (size_t)m0 * IN_F);
#pragma unroll
    for (int w = 0; w < 16; ++w) {
        int idx4 = tid + w * 256;
        int row = idx4 >> 4;
        int i0 = (idx4 & 15) * 4;
        float4 v = xsrc[idx4];
        xs[(i0 + 0) * XS_STRIDE + row] = v.x;
        xs[(i0 + 1) * XS_STRIDE + row] = v.y;
        xs[(i0 + 2) * XS_STRIDE + row] = v.z;
        xs[(i0 + 3) * XS_STRIDE + row] = v.w;
    }
    __syncthreads();

    // Prologue: B loads for stages 0 and 1
    if (tid == 0) {
        mbar_expect_tx(mb0, B_TILE_BYTES);
        bulk_g2s(BsU, g_packB, B_TILE_BYTES, mb0);
        mbar_expect_tx(mb1, B_TILE_BYTES);
        bulk_g2s(BsU + B_TILE_BYTES, g_packB + B_TILE_U32, B_TILE_BYTES, mb1);
    }

    float acc0[8][4], acc1[8][4];
#pragma unroll
    for (int nt = 0; nt < 8; ++nt)
#pragma unroll
        for (int q = 0; q < 4; ++q) { acc0[nt][q] = 0.f; acc1[nt][q] = 0.f; }

    int rbase = warp * 32 + gid;
    float m0f = (float)(2 * tig + 1);     // base mode for this thread's k-pairs

#pragma unroll 1
    for (int i = 0; i < NSTAGE; ++i) {
        // ---- A chains: per row, half2 mode-pairs (m0+8t, m0+8t+1), t=0..3 ----
        uint32_t pS[4][4], pC[4][4];
#pragma unroll
        for (int r = 0; r < 4; ++r) {
            float a = PI_F * xs[i * XS_STRIDE + rbase + 8 * r];
            float s1, c1; __sincosf(a, &s1, &c1);
            float sA, cA; __sincosf(m0f * a, &sA, &cA);     // mode m0 = 2tig+1
            float sB = fmaf(sA, c1,  cA * s1);              // mode m0+1
            float cB = fmaf(cA, c1, -sA * s1);
            float s2 = 2.f * s1 * c1, c2 = fmaf(-2.f * s1, s1, 1.f);
            float s4 = 2.f * s2 * c2, c4 = fmaf(-2.f * s2, s2, 1.f);
            float s8 = 2.f * s4 * c4, c8 = fmaf(-2.f * s4, s4, 1.f);
#pragma unroll
            for (int t = 0; t < 4; ++t) {
                pS[r][t] = pack_h2(sA, sB);
                pC[r][t] = pack_h2(cA, cB);
                float ns = fmaf(sA, c8,  cA * s8);
                cA = fmaf(cA, c8, -sA * s8); sA = ns;
                ns = fmaf(sB, c8,  cB * s8);
                cB = fmaf(cB, c8, -sB * s8); sB = ns;
            }
        }

        mbar_wait(i & 1 ? mb1 : mb0, (i >> 1) & 1);
        const uint32_t* Lp = Bs + (i & 1) * B_TILE_U32 + lane * 64;
        uint32_t lsw = (uint32_t)(lane & 15);

        // 4 k16-steps: j=0,1 use sin pairs; j=2,3 use cos pairs
#pragma unroll
        for (int h = 0; h < 2; ++h) {
#pragma unroll
            for (int jj = 0; jj < 2; ++jj) {
                int j = h * 2 + jj;
                uint32_t a0, a1, a2, a3, a4, a5, a6, a7;
                if (h == 0) {
                    a0 = pS[0][2*jj]; a1 = pS[1][2*jj]; a2 = pS[0][2*jj+1]; a3 = pS[1][2*jj+1];
                    a4 = pS[2][2*jj]; a5 = pS[3][2*jj]; a6 = pS[2][2*jj+1]; a7 = pS[3][2*jj+1];
                } else {
                    a0 = pC[0][2*jj]; a1 = pC[1][2*jj]; a2 = pC[0][2*jj+1]; a3 = pC[1][2*jj+1];
                    a4 = pC[2][2*jj]; a5 = pC[3][2*jj]; a6 = pC[2][2*jj+1]; a7 = pC[3][2*jj+1];
                }
#pragma unroll
                for (int np = 0; np < 4; ++np) {
                    uint32_t q = (uint32_t)(j * 4 + np);
                    const uint4 bv = *reinterpret_cast<const uint4*>(Lp + ((q ^ lsw) * 4));
                    int nt0 = 2 * np, nt1 = nt0 + 1;
                    mma_f16(acc0[nt0], a0, a1, a2, a3, bv.x, bv.y);
                    mma_f16(acc1[nt0], a4, a5, a6, a7, bv.x, bv.y);
                    mma_f16(acc0[nt1], a0, a1, a2, a3, bv.z, bv.w);
                    mma_f16(acc1[nt1], a4, a5, a6, a7, bv.z, bv.w);
                }
            }
        }
        __syncthreads();   // all warps done with buffer (i&1) before refill
        if (i + 2 < NSTAGE && tid == 0) {
            uint32_t mb = (i & 1) ? mb1 : mb0;
            mbar_expect_tx(mb, B_TILE_BYTES);
            bulk_g2s(BsU + (i & 1) * B_TILE_BYTES,
                     g_packB + (size_t)(i + 2) * B_TILE_U32, B_TILE_BYTES, mb);
        }
    }

    // ---- Epilogue: bias + fp32 stores (rows rbase+{0,8,16,24}) ----
    int c0 = tig * 2;
#pragma unroll
    for (int nt = 0; nt < 8; ++nt) {
        float bv0 = g_bias_eff[nt * 8 + c0];
        float bv1 = g_bias_eff[nt * 8 + c0 + 1];
        float* p0 = out + (size_t)(m0 + rbase) * OUT_F + nt * 8 + c0;
        float* p1 = out + (size_t)(m0 + rbase + 8) * OUT_F + nt * 8 + c0;
        float* p2 = out + (size_t)(m0 + rbase + 16) * OUT_F + nt * 8 + c0;
        float* p3 = out + (size_t)(m0 + rbase + 24) * OUT_F + nt * 8 + c0;
        *reinterpret_cast<float2*>(p0) = make_float2(acc0[nt][0] + bv0, acc0[nt][1] + bv1);
        *reinterpret_cast<float2*>(p1) = make_float2(acc0[nt][2] + bv0, acc0[nt][3] + bv1);
        *reinterpret_cast<float2*>(p2) = make_float2(acc1[nt][0] + bv0, acc1[nt][1] + bv1);
        *reinterpret_cast<float2*>(p3) = make_float2(acc1[nt][2] + bv0, acc1[nt][3] + bv1);
    }
}

// ---------------------------------------------------------------------------
extern "C" void kernel_launch(void* const* d_in, const int* in_sizes, int n_in,
                              void* d_out, int out_size) {
    const float* x      = (const float*)d_in[0];   // [N, 64] f32
    const float* coeffs = (const float*)d_in[1];   // [64, 64, 65] f32
    const float* bias   = (const float*)d_in[2];   // [64] f32
    float* out = (float*)d_out;

    int ntok = in_sizes[0] / IN_F;

    repack_kernel<<<(NSTAGE * 32 * 16 * 4 + 255) / 256, 256>>>(coeffs);
    bias_kernel<<<1, 64>>>(coeffs, bias);

    int smem_bytes = (NSTAGE * XS_STRIDE) * 4 + 2 * B_TILE_BYTES + 16;
    cudaFuncSetAttribute(fkan_main, cudaFuncAttributeMaxDynamicSharedMemorySize, smem_bytes);
    fkan_main<<<ntok / M_TILE, 256, smem_bytes>>>(x, out);
}